// round 1
// baseline (speedup 1.0000x reference)
#include <cuda_runtime.h>

// Problem constants
#define BB 4
#define NN 4096
#define CC 64

// Tiles for main kernel
#define TI 64
#define TJ 64

// Scratch (allocation-free rule: __device__ globals)
__device__ float g_out[BB * NN * CC];   // out = X @ W1
__device__ float g_sl[BB * NN];         // out @ alpha[:64]
__device__ float g_sr[BB * NN];         // out @ alpha[64:]
__device__ float g_agg[BB * NN * CC];   // attention-aggregated features

// ---------------------------------------------------------------------------
// Kernel 1: out = X @ W1 ; sl = out . alpha_l ; sr = out . alpha_r
// One block = 4 rows x 64 channels (256 threads).
// ---------------------------------------------------------------------------
__global__ __launch_bounds__(256) void prep_kernel(
    const float* __restrict__ X,
    const float* __restrict__ W1,
    const float* __restrict__ alpha)
{
    __shared__ float W1s[64 * 64];
    __shared__ float al[64], ar[64];
    __shared__ float Xs[4][64];
    __shared__ float slp[4][2], srp[4][2];

    int tid = threadIdx.x;
    for (int k = tid; k < 64 * 64; k += 256) W1s[k] = W1[k];
    if (tid < 64)       al[tid]      = alpha[tid];
    else if (tid < 128) ar[tid - 64] = alpha[tid];

    int row0 = blockIdx.x * 4;      // global row in [0, B*N)
    int r = tid >> 6;               // 0..3
    int c = tid & 63;               // 0..63
    Xs[r][c] = X[(row0 + r) * CC + c];
    __syncthreads();

    float acc = 0.f;
#pragma unroll
    for (int k = 0; k < 64; k++) acc += Xs[r][k] * W1s[k * 64 + c];
    g_out[(row0 + r) * CC + c] = acc;

    // reduce acc*alpha over c (64 threads = 2 warps per row)
    float vl = acc * al[c];
    float vr = acc * ar[c];
#pragma unroll
    for (int o = 16; o > 0; o >>= 1) {
        vl += __shfl_down_sync(0xffffffffu, vl, o);
        vr += __shfl_down_sync(0xffffffffu, vr, o);
    }
    if ((c & 31) == 0) { slp[r][c >> 5] = vl; srp[r][c >> 5] = vr; }
    __syncthreads();
    if (c == 0) {
        g_sl[row0 + r] = slp[r][0] + slp[r][1];
        g_sr[row0 + r] = srp[r][0] + srp[r][1];
    }
}

// ---------------------------------------------------------------------------
// Kernel 2: fused attention + aggregation.
//   w[i][j]  = exp(leaky_relu(sl_i * sr_j)) * adj[i][j]   (adj diag forced 1)
//   agg[i,c] = (sum_j w[i][j] * out[j,c]) / (sum_j w[i][j])
// Block tile: 64 i x 64 c (one batch). 256 threads, 4i x 4c register tile.
// ---------------------------------------------------------------------------
__global__ __launch_bounds__(256) void attn_kernel(const float* __restrict__ A_)
{
    __shared__ float wT[TJ][TI + 1];     // transposed w tile, padded (conflict-free)
    __shared__ float outs[TJ][CC];       // out[j, c] tile
    __shared__ float sls[TI];
    __shared__ float Zsh[TI];

    const int b      = blockIdx.y;
    const int i_base = blockIdx.x * TI;
    const int tid    = threadIdx.x;
    const int tx     = tid & 15;         // c group: channels 4*tx .. 4*tx+3
    const int ty     = tid >> 4;         // i group: rows     4*ty .. 4*ty+3

    if (tid < TI) sls[tid] = g_sl[b * NN + i_base + tid];

    const float* __restrict__ outb = g_out + (size_t)b * NN * CC;
    const float* __restrict__ srb  = g_sr + b * NN;

    float acc[4][4];
#pragma unroll
    for (int q = 0; q < 4; q++)
#pragma unroll
        for (int r = 0; r < 4; r++) acc[q][r] = 0.f;
    float Zacc[4] = {0.f, 0.f, 0.f, 0.f};

    // per-thread fixed j within tile (for w construction)
    const int jj  = tid & 63;
    const int ii0 = tid >> 6;

    for (int j_base = 0; j_base < NN; j_base += TJ) {
        __syncthreads();   // previous tile's reads done

        // stage out[j, :] tile (64x64 floats via float4)
#pragma unroll
        for (int k = 0; k < 4; k++) {
            int l   = tid + k * 256;     // 0..1023
            int jr  = l >> 4;
            int c4  = l & 15;
            float4 v = reinterpret_cast<const float4*>(outb + (size_t)(j_base + jr) * CC)[c4];
            reinterpret_cast<float4*>(&outs[jr][0])[c4] = v;
        }

        // construct w tile (transposed store, conflict-free by +1 pad)
        {
            int   gj   = j_base + jj;
            float sr_j = srb[gj];
#pragma unroll
            for (int k = 0; k < 16; k++) {
                int   ii  = ii0 + 4 * k;
                int   gi  = i_base + ii;
                float adj = A_[(size_t)gi * NN + gj];
                if (gi == gj) adj = 1.0f;
                float s  = sls[ii] * sr_j;
                float sc = s > 0.f ? s : 0.01f * s;   // leaky_relu(0.01)
                wT[jj][ii] = __expf(sc) * adj;
            }
        }
        __syncthreads();

        // FMA over the tile
#pragma unroll 8
        for (int j = 0; j < TJ; j++) {
            float4 ov = reinterpret_cast<const float4*>(&outs[j][0])[tx];
            float w0 = wT[j][4 * ty + 0];
            float w1 = wT[j][4 * ty + 1];
            float w2 = wT[j][4 * ty + 2];
            float w3 = wT[j][4 * ty + 3];
            acc[0][0] += w0 * ov.x; acc[0][1] += w0 * ov.y; acc[0][2] += w0 * ov.z; acc[0][3] += w0 * ov.w;
            acc[1][0] += w1 * ov.x; acc[1][1] += w1 * ov.y; acc[1][2] += w1 * ov.z; acc[1][3] += w1 * ov.w;
            acc[2][0] += w2 * ov.x; acc[2][1] += w2 * ov.y; acc[2][2] += w2 * ov.z; acc[2][3] += w2 * ov.w;
            acc[3][0] += w3 * ov.x; acc[3][1] += w3 * ov.y; acc[3][2] += w3 * ov.z; acc[3][3] += w3 * ov.w;
            if (tx == 0) {
                Zacc[0] += w0; Zacc[1] += w1; Zacc[2] += w2; Zacc[3] += w3;
            }
        }
    }

    if (tx == 0) {
#pragma unroll
        for (int q = 0; q < 4; q++) Zsh[4 * ty + q] = Zacc[q];
    }
    __syncthreads();

#pragma unroll
    for (int q = 0; q < 4; q++) {
        float invZ = 1.0f / Zsh[4 * ty + q];
        int   gi   = i_base + 4 * ty + q;
        float4 v = make_float4(acc[q][0] * invZ, acc[q][1] * invZ,
                               acc[q][2] * invZ, acc[q][3] * invZ);
        reinterpret_cast<float4*>(g_agg + ((size_t)b * NN + gi) * CC)[tx] = v;
    }
}

// ---------------------------------------------------------------------------
// Kernel 3: final = agg @ W2
// ---------------------------------------------------------------------------
__global__ __launch_bounds__(256) void finish_kernel(
    const float* __restrict__ W2, float* __restrict__ out)
{
    __shared__ float W2s[64 * 64];
    __shared__ float aggs[4][64];

    int tid = threadIdx.x;
    for (int k = tid; k < 64 * 64; k += 256) W2s[k] = W2[k];

    int row0 = blockIdx.x * 4;
    int r = tid >> 6;
    int c = tid & 63;
    aggs[r][c] = g_agg[(row0 + r) * CC + c];
    __syncthreads();

    float acc = 0.f;
#pragma unroll
    for (int k = 0; k < 64; k++) acc += aggs[r][k] * W2s[k * 64 + c];
    out[(row0 + r) * CC + c] = acc;
}

// ---------------------------------------------------------------------------
extern "C" void kernel_launch(void* const* d_in, const int* in_sizes, int n_in,
                              void* d_out, int out_size)
{
    (void)in_sizes; (void)n_in; (void)out_size;
    const float* X  = (const float*)d_in[0];   // (4, 4096, 64)
    const float* A_ = (const float*)d_in[1];   // (4096, 4096)
    const float* W1 = (const float*)d_in[2];   // (64, 64)
    const float* W2 = (const float*)d_in[3];   // (64, 64)
    const float* al = (const float*)d_in[4];   // (128, 1)
    float* out = (float*)d_out;                // (4, 4096, 64)

    prep_kernel<<<BB * NN / 4, 256>>>(X, W1, al);

    dim3 grid(NN / TI, BB);
    attn_kernel<<<grid, 256>>>(A_);

    finish_kernel<<<BB * NN / 4, 256>>>(W2, out);
}

// round 2
// speedup vs baseline: 1.8205x; 1.8205x over previous
#include <cuda_runtime.h>

#define BB 4
#define NN 4096
#define CC 64
#define CEXT 80            // 64 channels + ones col (64) + 15 zero pad
#define TI 128             // i rows per block
#define TJ 64              // j per stage
#define NSTAGES (NN / TJ)  // 64

// scratch (__device__ globals: allocation-free rule)
__device__ float g_outT[BB * CEXT * NN];  // [b][c][n] tf32; row 64 = ones, 65..79 = 0
__device__ float g_sl[BB * NN];
__device__ float g_sr[BB * NN];

__device__ __forceinline__ unsigned tf32_bits(float x) {
    unsigned u;
    asm("cvt.rna.tf32.f32 %0, %1;" : "=r"(u) : "f"(x));
    return u;
}

__device__ __forceinline__ void mma_tf32(float d[4], const unsigned a[4],
                                         unsigned b0, unsigned b1) {
    asm volatile(
        "mma.sync.aligned.m16n8k8.row.col.f32.tf32.tf32.f32 "
        "{%0,%1,%2,%3},{%4,%5,%6,%7},{%8,%9},{%0,%1,%2,%3};"
        : "+f"(d[0]), "+f"(d[1]), "+f"(d[2]), "+f"(d[3])
        : "r"(a[0]), "r"(a[1]), "r"(a[2]), "r"(a[3]), "r"(b0), "r"(b1));
}

// ---------------------------------------------------------------------------
// prep: out = X@W1 (not stored); g_outT[b][c][n] = tf32(out), +ones/zero rows;
//       g_sl = out.alpha_l ; g_sr = out.alpha_r
// block = 64 rows, 256 threads (thread: row=tid>>2, cols (tid&3)+4q)
// ---------------------------------------------------------------------------
__global__ __launch_bounds__(256) void prep_kernel(
    const float* __restrict__ X, const float* __restrict__ W1,
    const float* __restrict__ alpha)
{
    __shared__ float W1s[64 * 64];
    __shared__ float Xs[64 * 65];
    __shared__ float al[64], ar[64];

    const int tid = threadIdx.x;
    const int gr0 = blockIdx.x * 64;
    const int b0  = gr0 >> 12;
    const int n0  = gr0 & (NN - 1);

    for (int i = tid; i < 1024; i += 256)
        reinterpret_cast<float4*>(W1s)[i] = reinterpret_cast<const float4*>(W1)[i];
    for (int i = tid; i < 1024; i += 256) {
        int r = i >> 4, q = i & 15;
        float4 v = reinterpret_cast<const float4*>(X + (size_t)(gr0 + r) * CC)[q];
        Xs[r * 65 + 4 * q + 0] = v.x; Xs[r * 65 + 4 * q + 1] = v.y;
        Xs[r * 65 + 4 * q + 2] = v.z; Xs[r * 65 + 4 * q + 3] = v.w;
    }
    if (tid < 64)       al[tid]      = alpha[tid];
    else if (tid < 128) ar[tid - 64] = alpha[tid];
    __syncthreads();

    const int r  = tid >> 2;   // 0..63
    const int c0 = tid & 3;    // cols c0 + 4q

    float acc[16];
#pragma unroll
    for (int q = 0; q < 16; q++) acc[q] = 0.f;
#pragma unroll 8
    for (int k = 0; k < 64; k++) {
        float xv = Xs[r * 65 + k];
#pragma unroll
        for (int q = 0; q < 16; q++) acc[q] += xv * W1s[k * 64 + c0 + 4 * q];
    }

    float vl = 0.f, vr = 0.f;
#pragma unroll
    for (int q = 0; q < 16; q++) {
        vl += acc[q] * al[c0 + 4 * q];
        vr += acc[q] * ar[c0 + 4 * q];
    }
    vl += __shfl_xor_sync(0xffffffffu, vl, 1);
    vl += __shfl_xor_sync(0xffffffffu, vl, 2);
    vr += __shfl_xor_sync(0xffffffffu, vr, 1);
    vr += __shfl_xor_sync(0xffffffffu, vr, 2);

    const int gr = gr0 + r;
    const int n  = gr & (NN - 1);
    if (c0 == 0) { g_sl[gr] = vl; g_sr[gr] = vr; }

    unsigned* oT = reinterpret_cast<unsigned*>(g_outT);
    size_t base = (size_t)b0 * CEXT * NN + n;
#pragma unroll
    for (int q = 0; q < 16; q++)
        oT[base + (size_t)(c0 + 4 * q) * NN] = tf32_bits(acc[q]);

    // ones row (c=64) and zero rows (65..79) for this block's 64 n's
#pragma unroll
    for (int p = 0; p < 4; p++) {
        int it = tid + 256 * p;           // 0..1023
        int rr = 64 + (it >> 6);          // 64..79
        int nn = n0 + (it & 63);
        g_outT[(size_t)b0 * CEXT * NN + (size_t)rr * NN + nn] = (rr == 64) ? 1.0f : 0.0f;
    }
}

// ---------------------------------------------------------------------------
// attn: per block (b, 128 i-rows):
//   w[i][j] = exp(leaky_relu(sl_i*sr_j)) * adj   (diag forced 1)
//   D = w @ outT^T via tf32 mma.sync (C_ext=80; col 64 = Z row-sum)
//   agg = D[:, :64] / Z ;  out = agg @ W2  (fused epilogue)
// 256 threads = 8 warps: wm = wid&3 (32 i each), wn = wid>>2 (40 c each)
// ---------------------------------------------------------------------------
#define WS_STRIDE 68
#define SM_WS0   0
#define SM_WS1   (128 * WS_STRIDE)
#define SM_OS0   (2 * 128 * WS_STRIDE)
#define SM_OS1   (SM_OS0 + 80 * WS_STRIDE)
#define SM_W2    (SM_OS0 + 2 * 80 * WS_STRIDE)
#define SM_SLS   (SM_W2 + 64 * 64)
#define SM_ZSH   (SM_SLS + 128)
#define SMEM_FLOATS (SM_ZSH + 128)
#define SMEM_BYTES (SMEM_FLOATS * 4)

__global__ void __launch_bounds__(256, 1) attn_kernel(
    const float* __restrict__ A_, const float* __restrict__ W2,
    float* __restrict__ out)
{
    extern __shared__ float sm[];
    float* wS0 = sm + SM_WS0;
    float* wS1 = sm + SM_WS1;
    float* oS0 = sm + SM_OS0;
    float* oS1 = sm + SM_OS1;
    float* W2s = sm + SM_W2;
    float* sls = sm + SM_SLS;
    float* Zsh = sm + SM_ZSH;

    const int b      = blockIdx.y;
    const int i_base = blockIdx.x * TI;
    const int tid    = threadIdx.x;

    for (int i = tid; i < 1024; i += 256)
        reinterpret_cast<float4*>(W2s)[i] = reinterpret_cast<const float4*>(W2)[i];
    if (tid < 128) sls[tid] = g_sl[b * NN + i_base + tid];

    const int jj  = tid & 63;
    const int ii0 = tid >> 6;
    const float* Abase = A_ + (size_t)(i_base + ii0) * NN + jj;
    const float* oTb   = g_outT + (size_t)b * CEXT * NN;
    const float* srb   = g_sr + b * NN;

    float  av[32];
    float4 ov[5];
    float  srv;

    auto preload = [&](int s) {
        const int jb = s * TJ;
        const float* ap = Abase + jb;
#pragma unroll
        for (int k = 0; k < 32; k++) av[k] = __ldg(ap + (size_t)(4 * k) * NN);
        srv = __ldg(srb + jb + jj);
#pragma unroll
        for (int p = 0; p < 5; p++) {
            int it = tid + 256 * p;
            int rr = it >> 4, q = it & 15;
            ov[p] = *reinterpret_cast<const float4*>(oTb + (size_t)rr * NN + jb + 4 * q);
        }
    };
    auto commit = [&](int s, float* w, float* o) {
        const int gj = s * TJ + jj;
        unsigned* wu = reinterpret_cast<unsigned*>(w);
#pragma unroll
        for (int k = 0; k < 32; k++) {
            int ii = ii0 + 4 * k;
            int gi = i_base + ii;
            float adj = (gi == gj) ? 1.0f : av[k];
            float sc = sls[ii] * srv;
            sc = sc > 0.f ? sc : 0.01f * sc;
            float wv = __expf(sc) * adj;
            wu[ii * WS_STRIDE + jj] = tf32_bits(wv);
        }
#pragma unroll
        for (int p = 0; p < 5; p++) {
            int it = tid + 256 * p;
            int rr = it >> 4, q = it & 15;
            *reinterpret_cast<float4*>(o + rr * WS_STRIDE + 4 * q) = ov[p];
        }
    };

    float acc[2][5][4];
#pragma unroll
    for (int mt = 0; mt < 2; mt++)
#pragma unroll
        for (int nt = 0; nt < 5; nt++)
#pragma unroll
            for (int e = 0; e < 4; e++) acc[mt][nt][e] = 0.f;

    const int lane = tid & 31, wid = tid >> 5;
    const int wm = wid & 3, wn = wid >> 2;
    const int r = lane >> 2, cq = lane & 3;
    const int moff = wm * 32, noff = wn * 40;

    preload(0);
    __syncthreads();           // sls/W2s visible
    commit(0, wS0, oS0);
    preload(1);
    __syncthreads();

    for (int s = 0; s < NSTAGES; s++) {
        float* wc = (s & 1) ? wS1 : wS0;
        float* oc = (s & 1) ? oS1 : oS0;
        if (s + 1 < NSTAGES) commit(s + 1, (s & 1) ? wS0 : wS1, (s & 1) ? oS0 : oS1);
        if (s + 2 < NSTAGES) preload(s + 2);

#pragma unroll
        for (int ks = 0; ks < 8; ks++) {
            const int ko = ks * 8;
            unsigned a[2][4];
#pragma unroll
            for (int mt = 0; mt < 2; mt++) {
                int rr = moff + mt * 16 + r;
                a[mt][0] = __float_as_uint(wc[rr * WS_STRIDE + ko + cq]);
                a[mt][1] = __float_as_uint(wc[(rr + 8) * WS_STRIDE + ko + cq]);
                a[mt][2] = __float_as_uint(wc[rr * WS_STRIDE + ko + cq + 4]);
                a[mt][3] = __float_as_uint(wc[(rr + 8) * WS_STRIDE + ko + cq + 4]);
            }
#pragma unroll
            for (int nt = 0; nt < 5; nt++) {
                int nn = noff + nt * 8 + r;
                unsigned b0 = __float_as_uint(oc[nn * WS_STRIDE + ko + cq]);
                unsigned b1 = __float_as_uint(oc[nn * WS_STRIDE + ko + cq + 4]);
                mma_tf32(acc[0][nt], a[0], b0, b1);
                mma_tf32(acc[1][nt], a[1], b0, b1);
            }
        }
        __syncthreads();
    }

    // Z = D[:, 64] (ones column) lives in wn==1, nt==3, frag col 0 (cq==0)
    if (wn == 1 && cq == 0) {
#pragma unroll
        for (int mt = 0; mt < 2; mt++) {
            int rr = moff + mt * 16 + r;
            Zsh[rr]     = acc[mt][3][0];
            Zsh[rr + 8] = acc[mt][3][2];
        }
    }
    __syncthreads();

    float* aggS = wS0;  // reuse
    const int ntmax = (wn == 0) ? 5 : 3;
#pragma unroll
    for (int mt = 0; mt < 2; mt++) {
        int rr = moff + mt * 16 + r;
        float z0 = 1.0f / Zsh[rr];
        float z1 = 1.0f / Zsh[rr + 8];
#pragma unroll
        for (int nt = 0; nt < 5; nt++) {
            if (nt >= ntmax) break;
            int col = noff + nt * 8 + 2 * cq;
            aggS[rr * WS_STRIDE + col]           = acc[mt][nt][0] * z0;
            aggS[rr * WS_STRIDE + col + 1]       = acc[mt][nt][1] * z0;
            aggS[(rr + 8) * WS_STRIDE + col]     = acc[mt][nt][2] * z1;
            aggS[(rr + 8) * WS_STRIDE + col + 1] = acc[mt][nt][3] * z1;
        }
    }
    __syncthreads();

    // epilogue GEMM: out = aggS(128x64) @ W2(64x64)
    const int r0 = tid >> 2;
    const int c0 = tid & 3;
    float res0[16], res1[16];
#pragma unroll
    for (int q = 0; q < 16; q++) { res0[q] = 0.f; res1[q] = 0.f; }
#pragma unroll 8
    for (int k = 0; k < 64; k++) {
        float a0 = aggS[r0 * WS_STRIDE + k];
        float a1 = aggS[(r0 + 64) * WS_STRIDE + k];
#pragma unroll
        for (int q = 0; q < 16; q++) {
            float wv = W2s[k * 64 + c0 + 4 * q];
            res0[q] += a0 * wv;
            res1[q] += a1 * wv;
        }
    }
    float* ob = out + (size_t)(b * NN + i_base) * CC;
#pragma unroll
    for (int q = 0; q < 16; q++) {
        ob[r0 * CC + c0 + 4 * q]        = res0[q];
        ob[(r0 + 64) * CC + c0 + 4 * q] = res1[q];
    }
}

// ---------------------------------------------------------------------------
extern "C" void kernel_launch(void* const* d_in, const int* in_sizes, int n_in,
                              void* d_out, int out_size)
{
    (void)in_sizes; (void)n_in; (void)out_size;
    const float* X  = (const float*)d_in[0];
    const float* A_ = (const float*)d_in[1];
    const float* W1 = (const float*)d_in[2];
    const float* W2 = (const float*)d_in[3];
    const float* al = (const float*)d_in[4];
    float* out = (float*)d_out;

    cudaFuncSetAttribute(attn_kernel, cudaFuncAttributeMaxDynamicSharedMemorySize,
                         SMEM_BYTES);

    prep_kernel<<<BB * NN / 64, 256>>>(X, W1, al);

    dim3 grid(NN / TI, BB);
    attn_kernel<<<grid, 256, SMEM_BYTES>>>(A_, W2, out);
}

// round 3
// speedup vs baseline: 2.9315x; 1.6103x over previous
#include <cuda_runtime.h>

#define BB 4
#define NN 4096
#define CC 64
#define CEXT 80            // 64 channels + ones col (64) + 15 zero pad
#define TI 128             // i rows per block
#define TJ 64              // j per stage
#define NSTAGES (NN / TJ)  // 64

__device__ float g_outT[BB * CEXT * NN];  // [b][c][n] tf32; row 64 = ones, 65..79 = 0
__device__ float g_sl[BB * NN];
__device__ float g_sr[BB * NN];

__device__ __forceinline__ unsigned tf32_bits(float x) {
    unsigned u;
    asm("cvt.rna.tf32.f32 %0, %1;" : "=r"(u) : "f"(x));
    return u;
}

__device__ __forceinline__ void mma_tf32(float d[4], const unsigned a[4],
                                         unsigned b0, unsigned b1) {
    asm volatile(
        "mma.sync.aligned.m16n8k8.row.col.f32.tf32.tf32.f32 "
        "{%0,%1,%2,%3},{%4,%5,%6,%7},{%8,%9},{%0,%1,%2,%3};"
        : "+f"(d[0]), "+f"(d[1]), "+f"(d[2]), "+f"(d[3])
        : "r"(a[0]), "r"(a[1]), "r"(a[2]), "r"(a[3]), "r"(b0), "r"(b1));
}

#define BAR_SYNC(id)   asm volatile("bar.sync %0, 512;"   :: "r"(id) : "memory")
#define BAR_ARRIVE(id) asm volatile("bar.arrive %0, 512;" :: "r"(id) : "memory")

// ---------------------------------------------------------------------------
// prep: out = X@W1 ; g_outT = tf32(out)^T (+ones/zero rows); g_sl, g_sr
// block = 64 rows, 256 threads. thread: row = tid>>2, cols 16*(tid&3)+q
// ---------------------------------------------------------------------------
__global__ __launch_bounds__(256) void prep_kernel(
    const float* __restrict__ X, const float* __restrict__ W1,
    const float* __restrict__ alpha)
{
    __shared__ float W1s[64 * 64];
    __shared__ float Xs[64 * 65];
    __shared__ float al[64], ar[64];

    const int tid = threadIdx.x;
    const int gr0 = blockIdx.x * 64;
    const int b0  = gr0 >> 12;
    const int n0  = gr0 & (NN - 1);

    for (int i = tid; i < 1024; i += 256)
        reinterpret_cast<float4*>(W1s)[i] = reinterpret_cast<const float4*>(W1)[i];
    for (int i = tid; i < 1024; i += 256) {
        int r = i >> 4, q = i & 15;
        float4 v = reinterpret_cast<const float4*>(X + (size_t)(gr0 + r) * CC)[q];
        Xs[r * 65 + 4 * q + 0] = v.x; Xs[r * 65 + 4 * q + 1] = v.y;
        Xs[r * 65 + 4 * q + 2] = v.z; Xs[r * 65 + 4 * q + 3] = v.w;
    }
    if (tid < 64)       al[tid]      = alpha[tid];
    else if (tid < 128) ar[tid - 64] = alpha[tid];
    __syncthreads();

    const int r  = tid >> 2;          // 0..63
    const int c0 = tid & 3;           // cols 16*c0 + q, q<16

    float acc[16];
#pragma unroll
    for (int q = 0; q < 16; q++) acc[q] = 0.f;
    const float4* W1v = reinterpret_cast<const float4*>(W1s);
#pragma unroll 8
    for (int k = 0; k < 64; k++) {
        float xv = Xs[r * 65 + k];
#pragma unroll
        for (int h = 0; h < 4; h++) {
            float4 wv = W1v[k * 16 + 4 * c0 + h];
            acc[4 * h + 0] += xv * wv.x;
            acc[4 * h + 1] += xv * wv.y;
            acc[4 * h + 2] += xv * wv.z;
            acc[4 * h + 3] += xv * wv.w;
        }
    }

    float vl = 0.f, vr = 0.f;
#pragma unroll
    for (int q = 0; q < 16; q++) {
        vl += acc[q] * al[16 * c0 + q];
        vr += acc[q] * ar[16 * c0 + q];
    }
    vl += __shfl_xor_sync(0xffffffffu, vl, 1);
    vl += __shfl_xor_sync(0xffffffffu, vl, 2);
    vr += __shfl_xor_sync(0xffffffffu, vr, 1);
    vr += __shfl_xor_sync(0xffffffffu, vr, 2);

    const int gr = gr0 + r;
    const int n  = gr & (NN - 1);
    if (c0 == 0) { g_sl[gr] = vl; g_sr[gr] = vr; }

    unsigned* oT = reinterpret_cast<unsigned*>(g_outT);
    size_t base = (size_t)b0 * CEXT * NN + n;
#pragma unroll
    for (int q = 0; q < 16; q++)
        oT[base + (size_t)(16 * c0 + q) * NN] = tf32_bits(acc[q]);

#pragma unroll
    for (int p = 0; p < 4; p++) {
        int it = tid + 256 * p;
        int rr = 64 + (it >> 6);
        int nn = n0 + (it & 63);
        g_outT[(size_t)b0 * CEXT * NN + (size_t)rr * NN + nn] = (rr == 64) ? 1.0f : 0.0f;
    }
}

// ---------------------------------------------------------------------------
// attn (warp-specialized): 512 threads.
//   warps 0..7  : tf32 mma consumers (wm = wid&3 -> 32 i, wn = wid>>2 -> 40 c)
//   warps 8..15 : producers (build w tile, stage outT tile)
// ---------------------------------------------------------------------------
#define WS_STRIDE 68
#define SM_WS0   0
#define SM_WS1   (128 * WS_STRIDE)
#define SM_OS0   (2 * 128 * WS_STRIDE)
#define SM_OS1   (SM_OS0 + 80 * WS_STRIDE)
#define SM_W2    (SM_OS0 + 2 * 80 * WS_STRIDE)
#define SM_SLS   (SM_W2 + 64 * 64)
#define SM_ZSH   (SM_SLS + 128)
#define SMEM_FLOATS (SM_ZSH + 128)
#define SMEM_BYTES (SMEM_FLOATS * 4)

__global__ void __launch_bounds__(512, 1) attn_kernel(
    const float* __restrict__ A_, const float* __restrict__ W2,
    float* __restrict__ out)
{
    extern __shared__ float sm[];
    float* wS0 = sm + SM_WS0;
    float* wS1 = sm + SM_WS1;
    float* oS0 = sm + SM_OS0;
    float* oS1 = sm + SM_OS1;
    float* W2s = sm + SM_W2;
    float* sls = sm + SM_SLS;
    float* Zsh = sm + SM_ZSH;

    const int b      = blockIdx.y;
    const int i_base = blockIdx.x * TI;
    const int tid    = threadIdx.x;

    for (int i = tid; i < 1024; i += 512)
        reinterpret_cast<float4*>(W2s)[i] = reinterpret_cast<const float4*>(W2)[i];
    if (tid >= 256 && tid < 384) sls[tid - 256] = g_sl[b * NN + i_base + (tid - 256)];
    __syncthreads();

    if (tid < 256) {
        // ---------------- consumers ----------------
        const int lane = tid & 31, wid = tid >> 5;
        const int wm = wid & 3, wn = wid >> 2;
        const int r = lane >> 2, cq = lane & 3;
        const int moff = wm * 32, noff = wn * 40;

        float acc[2][5][4];
#pragma unroll
        for (int mt = 0; mt < 2; mt++)
#pragma unroll
            for (int nt = 0; nt < 5; nt++)
#pragma unroll
                for (int e = 0; e < 4; e++) acc[mt][nt][e] = 0.f;

        for (int s = 0; s < NSTAGES; s++) {
            const int buf = s & 1;
            BAR_SYNC(1 + buf);
            float* wc = buf ? wS1 : wS0;
            float* oc = buf ? oS1 : oS0;

#pragma unroll
            for (int ks = 0; ks < 8; ks++) {
                const int ko = ks * 8;
                unsigned a[2][4];
#pragma unroll
                for (int mt = 0; mt < 2; mt++) {
                    int rr = moff + mt * 16 + r;
                    a[mt][0] = __float_as_uint(wc[rr * WS_STRIDE + ko + cq]);
                    a[mt][1] = __float_as_uint(wc[(rr + 8) * WS_STRIDE + ko + cq]);
                    a[mt][2] = __float_as_uint(wc[rr * WS_STRIDE + ko + cq + 4]);
                    a[mt][3] = __float_as_uint(wc[(rr + 8) * WS_STRIDE + ko + cq + 4]);
                }
#pragma unroll
                for (int nt = 0; nt < 5; nt++) {
                    int nn = noff + nt * 8 + r;
                    unsigned b0 = __float_as_uint(oc[nn * WS_STRIDE + ko + cq]);
                    unsigned b1 = __float_as_uint(oc[nn * WS_STRIDE + ko + cq + 4]);
                    mma_tf32(acc[0][nt], a[0], b0, b1);
                    mma_tf32(acc[1][nt], a[1], b0, b1);
                }
            }
            BAR_ARRIVE(3 + buf);
        }

        // Z = ones column (col 64): wn==1, nt==3, cq==0
        if (wn == 1 && cq == 0) {
#pragma unroll
            for (int mt = 0; mt < 2; mt++) {
                int rr = moff + mt * 16 + r;
                Zsh[rr]     = acc[mt][3][0];
                Zsh[rr + 8] = acc[mt][3][2];
            }
        }
        __syncthreads();   // (A) joint with producers

        float* aggS = wS0;
        const int ntmax = (wn == 0) ? 5 : 3;
#pragma unroll
        for (int mt = 0; mt < 2; mt++) {
            int rr = moff + mt * 16 + r;
            float z0 = 1.0f / Zsh[rr];
            float z1 = 1.0f / Zsh[rr + 8];
#pragma unroll
            for (int nt = 0; nt < 5; nt++) {
                if (nt >= ntmax) break;
                int col = noff + nt * 8 + 2 * cq;
                aggS[rr * WS_STRIDE + col]           = acc[mt][nt][0] * z0;
                aggS[rr * WS_STRIDE + col + 1]       = acc[mt][nt][1] * z0;
                aggS[(rr + 8) * WS_STRIDE + col]     = acc[mt][nt][2] * z1;
                aggS[(rr + 8) * WS_STRIDE + col + 1] = acc[mt][nt][3] * z1;
            }
        }
    } else {
        // ---------------- producers ----------------
        const int ptid = tid - 256;        // 0..255
        const int jj4  = ptid & 15;        // j cols 4*jj4 .. +3
        const int rgrp = ptid >> 4;        // rows rgrp + 16*k

        const float* Abase = A_ + (size_t)(i_base + rgrp) * NN + 4 * jj4;
        const float* oTb   = g_outT + (size_t)b * CEXT * NN;
        const float* srb   = g_sr + b * NN + 4 * jj4;

        float4 a4[8], o4[5], sr4;

        auto preload = [&](int s) {
            const int jb = s * TJ;
#pragma unroll
            for (int k = 0; k < 8; k++)
                a4[k] = *reinterpret_cast<const float4*>(Abase + (size_t)(16 * k) * NN + jb);
            sr4 = *reinterpret_cast<const float4*>(srb + jb);
#pragma unroll
            for (int p = 0; p < 5; p++) {
                int it = ptid + 256 * p;
                int rr = it >> 4, q = it & 15;
                o4[p] = *reinterpret_cast<const float4*>(oTb + (size_t)rr * NN + jb + 4 * q);
            }
        };
        auto wcalc = [&](float slv, float srv, float adj) -> unsigned {
            float sc = slv * srv;
            sc = sc > 0.f ? sc : 0.01f * sc;
            return tf32_bits(__expf(sc) * adj);
        };
        auto commit = [&](int s, float* wbuf, float* obuf) {
            const int jb  = s * TJ;
            const int gj0 = jb + 4 * jj4;
            uint4* wu = reinterpret_cast<uint4*>(wbuf);
#pragma unroll
            for (int k = 0; k < 8; k++) {
                int ii = rgrp + 16 * k;
                int gi = i_base + ii;
                float slv = sls[ii];
                float4 a = a4[k];
                uint4 wv;
                wv.x = wcalc(slv, sr4.x, (gi == gj0 + 0) ? 1.f : a.x);
                wv.y = wcalc(slv, sr4.y, (gi == gj0 + 1) ? 1.f : a.y);
                wv.z = wcalc(slv, sr4.z, (gi == gj0 + 2) ? 1.f : a.z);
                wv.w = wcalc(slv, sr4.w, (gi == gj0 + 3) ? 1.f : a.w);
                wu[17 * ii + jj4] = wv;
            }
#pragma unroll
            for (int p = 0; p < 5; p++) {
                int it = ptid + 256 * p;
                int rr = it >> 4, q = it & 15;
                reinterpret_cast<float4*>(obuf)[17 * rr + q] = o4[p];
            }
        };

        preload(0);
        for (int s = 0; s < NSTAGES; s++) {
            const int buf = s & 1;
            if (s >= 2) BAR_SYNC(3 + buf);
            commit(s, buf ? wS1 : wS0, buf ? oS1 : oS0);
            BAR_ARRIVE(1 + buf);
            if (s + 1 < NSTAGES) preload(s + 1);
        }
        __syncthreads();   // (A) joint with consumers
    }

    __syncthreads();       // (B) aggS ready

    // epilogue GEMM: out = aggS(128x64) @ W2(64x64), all 512 threads
    const float* aggS = wS0;
    const int r0 = tid >> 2;        // 0..127
    const int c0 = tid & 3;
    float res[16];
#pragma unroll
    for (int q = 0; q < 16; q++) res[q] = 0.f;
#pragma unroll 8
    for (int k = 0; k < 64; k++) {
        float a0 = aggS[r0 * WS_STRIDE + k];
#pragma unroll
        for (int q = 0; q < 16; q++)
            res[q] += a0 * W2s[k * 64 + c0 + 4 * q];
    }
    float* ob = out + (size_t)(b * NN + i_base) * CC;
#pragma unroll
    for (int q = 0; q < 16; q++)
        ob[r0 * CC + c0 + 4 * q] = res[q];
}

// ---------------------------------------------------------------------------
extern "C" void kernel_launch(void* const* d_in, const int* in_sizes, int n_in,
                              void* d_out, int out_size)
{
    (void)in_sizes; (void)n_in; (void)out_size;
    const float* X  = (const float*)d_in[0];
    const float* A_ = (const float*)d_in[1];
    const float* W1 = (const float*)d_in[2];
    const float* W2 = (const float*)d_in[3];
    const float* al = (const float*)d_in[4];
    float* out = (float*)d_out;

    cudaFuncSetAttribute(attn_kernel, cudaFuncAttributeMaxDynamicSharedMemorySize,
                         SMEM_BYTES);

    prep_kernel<<<BB * NN / 64, 256>>>(X, W1, al);

    dim3 grid(NN / TI, BB);
    attn_kernel<<<grid, 512, SMEM_BYTES>>>(A_, W2, out);
}